// round 12
// baseline (speedup 1.0000x reference)
#include <cuda_runtime.h>
#include <cuda_fp16.h>
#include <math.h>
#include <stdint.h>

#define D_MODEL 1024
#define NUM_HEADS 16
#define DK 64
#define BATCH 4
#define SEQ 2048
#define MTOT (BATCH * SEQ)   // 8192

// Scratch (no allocation allowed) — fp16 intermediates
__device__ __half g_qh[MTOT * D_MODEL];
__device__ __half g_kh[MTOT * D_MODEL];
__device__ __half g_vh[MTOT * D_MODEL];
__device__ __half g_Qh[MTOT * D_MODEL];
__device__ __half g_Kh[MTOT * D_MODEL];
__device__ __half g_Vh[MTOT * D_MODEL];
__device__ __half g_Oh[MTOT * D_MODEL];
__device__ __half g_Wh[4 * D_MODEL * D_MODEL];

// ---------------------------------------------------------------------------
// Helpers
// ---------------------------------------------------------------------------
__device__ __forceinline__ uint32_t packh2(float a, float b) {
    __half2 h = __floats2half2_rn(a, b);
    return *reinterpret_cast<uint32_t*>(&h);
}
__device__ __forceinline__ uint32_t ex2h2(uint32_t x) {
    uint32_t r;
    asm("ex2.approx.f16x2 %0, %1;" : "=r"(r) : "r"(x));
    return r;
}

__device__ __forceinline__ void mma16(float c[4], uint32_t a0, uint32_t a1,
                                      uint32_t a2, uint32_t a3,
                                      uint32_t b0, uint32_t b1) {
    asm volatile(
        "mma.sync.aligned.m16n8k16.row.col.f32.f16.f16.f32 "
        "{%0,%1,%2,%3}, {%4,%5,%6,%7}, {%8,%9}, {%0,%1,%2,%3};"
        : "+f"(c[0]), "+f"(c[1]), "+f"(c[2]), "+f"(c[3])
        : "r"(a0), "r"(a1), "r"(a2), "r"(a3), "r"(b0), "r"(b1));
}

__device__ __forceinline__ void ldsm4(uint32_t r[4], uint32_t saddr) {
    asm volatile(
        "ldmatrix.sync.aligned.m8n8.x4.shared.b16 {%0,%1,%2,%3}, [%4];"
        : "=r"(r[0]), "=r"(r[1]), "=r"(r[2]), "=r"(r[3]) : "r"(saddr));
}
__device__ __forceinline__ void ldsm4t(uint32_t r[4], uint32_t saddr) {
    asm volatile(
        "ldmatrix.sync.aligned.m8n8.x4.trans.shared.b16 {%0,%1,%2,%3}, [%4];"
        : "=r"(r[0]), "=r"(r[1]), "=r"(r[2]), "=r"(r[3]) : "r"(saddr));
}

__device__ __forceinline__ void cp_async16(void* smem, const void* gmem) {
    uint32_t s = (uint32_t)__cvta_generic_to_shared(smem);
    asm volatile("cp.async.cg.shared.global [%0], [%1], 16;" :: "r"(s), "l"(gmem));
}
__device__ __forceinline__ void cp_commit() {
    asm volatile("cp.async.commit_group;");
}
template <int N>
__device__ __forceinline__ void cp_wait() {
    asm volatile("cp.async.wait_group %0;" :: "n"(N));
}

// ---------------------------------------------------------------------------
// Fused fp32->fp16 conversions
// ---------------------------------------------------------------------------
__global__ __launch_bounds__(256) void cvt3_f2h(
    const float* __restrict__ s0, const float* __restrict__ s1,
    const float* __restrict__ s2,
    __half* __restrict__ d0, __half* __restrict__ d1, __half* __restrict__ d2)
{
    const float* src = (blockIdx.y == 0) ? s0 : (blockIdx.y == 1) ? s1 : s2;
    __half* dst = (blockIdx.y == 0) ? d0 : (blockIdx.y == 1) ? d1 : d2;
    int i = (blockIdx.x * 256 + threadIdx.x) * 8;
    float4 v0 = *(const float4*)(src + i);
    float4 v1 = *(const float4*)(src + i + 4);
    __half2 h[4];
    h[0] = __floats2half2_rn(v0.x, v0.y);
    h[1] = __floats2half2_rn(v0.z, v0.w);
    h[2] = __floats2half2_rn(v1.x, v1.y);
    h[3] = __floats2half2_rn(v1.z, v1.w);
    *(uint4*)(dst + i) = *(uint4*)h;
}

__global__ __launch_bounds__(256) void cvt4_f2h(
    const float* __restrict__ s0, const float* __restrict__ s1,
    const float* __restrict__ s2, const float* __restrict__ s3,
    __half* __restrict__ dst)
{
    const float* src = (blockIdx.y == 0) ? s0 : (blockIdx.y == 1) ? s1
                       : (blockIdx.y == 2) ? s2 : s3;
    __half* d = dst + (size_t)blockIdx.y * D_MODEL * D_MODEL;
    int i = (blockIdx.x * 256 + threadIdx.x) * 8;
    float4 v0 = *(const float4*)(src + i);
    float4 v1 = *(const float4*)(src + i + 4);
    __half2 h[4];
    h[0] = __floats2half2_rn(v0.x, v0.y);
    h[1] = __floats2half2_rn(v0.z, v0.w);
    h[2] = __floats2half2_rn(v1.x, v1.y);
    h[3] = __floats2half2_rn(v1.z, v1.w);
    *(uint4*)(d + i) = *(uint4*)h;
}

// ---------------------------------------------------------------------------
// fp16 GEMM core: 128 thr, 4 warps (2x2), warp 64x64, BK=32, cp.async 4-stage.
// ---------------------------------------------------------------------------
#define HP 40
#define HSTG 4
#define HSTAGE (128 * HP)
#define GEMM_SMEM (HSTG * 2 * HSTAGE * 2)  // 81920 B

template <int OUT_HALF>
__device__ __forceinline__ void gemm_body(
    const __half* __restrict__ A, const __half* __restrict__ W,
    const float* __restrict__ bias, void* __restrict__ Cout)
{
    extern __shared__ __align__(16) __half sgh[];
    __half* As = sgh;
    __half* Ws = sgh + HSTG * HSTAGE;

    const int tid = threadIdx.x;
    const int lane = tid & 31;
    const int g = lane >> 2, tig = lane & 3;
    const int wid = tid >> 5;
    const int wm = wid & 1;
    const int wn = wid >> 1;
    const int row0 = blockIdx.y * 128;
    const int col0 = blockIdx.x * 128;

    const __half* Ag = A + (size_t)row0 * D_MODEL;
    const __half* Wg = W + (size_t)col0 * D_MODEL;

    const uint32_t sA = (uint32_t)__cvta_generic_to_shared(As);
    const uint32_t sW = (uint32_t)__cvta_generic_to_shared(Ws);

    auto load_stage = [&](int ch, int st) {
        const int kof = ch * 32;
#pragma unroll
        for (int j = 0; j < 4; j++) {
            int slot = tid + j * 128;
            int r = slot >> 2, c = (slot & 3) * 8;
            cp_async16(&As[st * HSTAGE + r * HP + c],
                       Ag + (size_t)r * D_MODEL + kof + c);
            cp_async16(&Ws[st * HSTAGE + r * HP + c],
                       Wg + (size_t)r * D_MODEL + kof + c);
        }
        cp_commit();
    };
    load_stage(0, 0);
    load_stage(1, 1);
    load_stage(2, 2);

    float acc[4][8][4];
#pragma unroll
    for (int mt = 0; mt < 4; mt++)
#pragma unroll
        for (int nt = 0; nt < 8; nt++)
#pragma unroll
            for (int i = 0; i < 4; i++) acc[mt][nt][i] = 0.0f;

    const int a_row = lane & 15;
    const int a_byt = (lane >> 4) << 4;
    const int b_row = (lane & 7) + ((lane >> 4) << 3);
    const int b_byt = ((lane >> 3) & 1) << 4;

    const int NCH = D_MODEL / 32;  // 32
    for (int ch = 0; ch < NCH; ch++) {
        const int p = ch & 3;
        if (ch < NCH - 2) cp_wait<2>();
        else if (ch == NCH - 2) cp_wait<1>();
        else cp_wait<0>();
        __syncthreads();
        if (ch + 3 < NCH) load_stage(ch + 3, (ch + 3) & 3);

        const uint32_t aBase = sA + p * (HSTAGE * 2);
        const uint32_t wBase = sW + p * (HSTAGE * 2);
#pragma unroll
        for (int kk = 0; kk < 2; kk++) {
            uint32_t ua[4][4];
#pragma unroll
            for (int mt = 0; mt < 4; mt++)
                ldsm4(ua[mt], aBase + (wm * 64 + mt * 16 + a_row) * (HP * 2)
                              + kk * 32 + a_byt);
#pragma unroll
            for (int nt2 = 0; nt2 < 4; nt2++) {
                uint32_t ub[4];
                ldsm4(ub, wBase + (wn * 64 + nt2 * 16 + b_row) * (HP * 2)
                          + kk * 32 + b_byt);
#pragma unroll
                for (int mt = 0; mt < 4; mt++) {
                    mma16(acc[mt][nt2 * 2],     ua[mt][0], ua[mt][1], ua[mt][2], ua[mt][3], ub[0], ub[1]);
                    mma16(acc[mt][nt2 * 2 + 1], ua[mt][0], ua[mt][1], ua[mt][2], ua[mt][3], ub[2], ub[3]);
                }
            }
        }
    }

#pragma unroll
    for (int mt = 0; mt < 4; mt++) {
        const int ra = row0 + wm * 64 + mt * 16 + g;
#pragma unroll
        for (int nt = 0; nt < 8; nt++) {
            const int col = col0 + wn * 64 + nt * 8 + 2 * tig;
            const float bz0 = bias[col], bz1 = bias[col + 1];
            float v0 = acc[mt][nt][0] + bz0, v1 = acc[mt][nt][1] + bz1;
            float v2 = acc[mt][nt][2] + bz0, v3 = acc[mt][nt][3] + bz1;
            if (OUT_HALF) {
                __half* C = (__half*)Cout;
                *(__half2*)(C + (size_t)ra * D_MODEL + col) = __floats2half2_rn(v0, v1);
                *(__half2*)(C + (size_t)(ra + 8) * D_MODEL + col) = __floats2half2_rn(v2, v3);
            } else {
                float* C = (float*)Cout;
                *(float2*)(C + (size_t)ra * D_MODEL + col) = make_float2(v0, v1);
                *(float2*)(C + (size_t)(ra + 8) * D_MODEL + col) = make_float2(v2, v3);
            }
        }
    }
}

// Fused Q/K/V projections: blockIdx.z selects (input, weight, bias, output).
__global__ __launch_bounds__(128, 2) void gemm_qkv(
    const __half* __restrict__ a0, const __half* __restrict__ a1,
    const __half* __restrict__ a2, const __half* __restrict__ Wall,
    const float* __restrict__ b0, const float* __restrict__ b1,
    const float* __restrict__ b2,
    __half* __restrict__ c0, __half* __restrict__ c1, __half* __restrict__ c2)
{
    const int z = blockIdx.z;
    const __half* A = (z == 0) ? a0 : (z == 1) ? a1 : a2;
    const float* bias = (z == 0) ? b0 : (z == 1) ? b1 : b2;
    __half* C = (z == 0) ? c0 : (z == 1) ? c1 : c2;
    gemm_body<1>(A, Wall + (size_t)z * D_MODEL * D_MODEL, bias, C);
}

// O projection (fp32 out)
__global__ __launch_bounds__(128, 2) void gemm_o(
    const __half* __restrict__ A, const __half* __restrict__ W,
    const float* __restrict__ bias, float* __restrict__ C)
{
    gemm_body<0>(A, W, bias, C);
}

// ---------------------------------------------------------------------------
// fp16 flash attention (round-10 grid, non-persistent) + warp-voted rescale
// skip. 128 threads, 4 warps x 32 q-rows, Bc=64, base-2 ex2 softmax,
// 3-stage K/V ring, single sync/iter.
// ---------------------------------------------------------------------------
#define AKP 72
#define NSTG 3
#define ATTN_SMEM (2 * NSTG * 64 * AKP * 2)  // 55296 B

__global__ __launch_bounds__(128, 2) void attn_h(
    const __half* __restrict__ Q, const __half* __restrict__ K,
    const __half* __restrict__ V, __half* __restrict__ O)
{
    extern __shared__ __align__(16) __half smh[];
    __half* Ks = smh;
    __half* Vs = smh + NSTG * 64 * AKP;
    __half* Qst = smh;                       // overlay

    const int tid = threadIdx.x;
    const int lane = tid & 31;
    const int g = lane >> 2, tig = lane & 3;
    const int wid = tid >> 5;
    const int qb = wid * 32;                 // warp covers 32 q-rows

    const int b = blockIdx.y >> 4;
    const int h = blockIdx.y & 15;
    const int q0 = blockIdx.x * 128;
    const size_t base = (size_t)b * SEQ * D_MODEL + (size_t)h * DK;

    // Stage Q scaled by 0.125*log2(e) -> base-2 scores out of the MMA.
    {
        const __half2 sc = __half2half2(__float2half(0.18033688f));
        for (int i = tid; i < 128 * 8; i += 128) {
            int r = i >> 3, c8 = (i & 7) * 8;
            uint4 raw = *(const uint4*)(Q + base + (size_t)(q0 + r) * D_MODEL + c8);
            __half2* hp = (__half2*)&raw;
            hp[0] = __hmul2(hp[0], sc); hp[1] = __hmul2(hp[1], sc);
            hp[2] = __hmul2(hp[2], sc); hp[3] = __hmul2(hp[3], sc);
            *(uint4*)&Qst[r * AKP + c8] = raw;
        }
    }
    __syncthreads();

    const uint32_t sQ = (uint32_t)__cvta_generic_to_shared(Qst);
    const uint32_t sK = (uint32_t)__cvta_generic_to_shared(Ks);
    const uint32_t sV = (uint32_t)__cvta_generic_to_shared(Vs);
    const int a_row = lane & 15;
    const int a_byt = (lane >> 4) << 4;
    const int b_row = (lane & 7) + ((lane >> 4) << 3);
    const int b_byt = ((lane >> 3) & 1) << 4;
    const int v_row = (lane & 7) + (((lane >> 3) & 1) << 3);
    const int v_byt = (lane >> 4) << 4;

    uint32_t qa[2][4][4];
#pragma unroll
    for (int mt = 0; mt < 2; mt++)
#pragma unroll
        for (int kk = 0; kk < 4; kk++)
            ldsm4(qa[mt][kk], sQ + (qb + mt * 16 + a_row) * (AKP * 2) + kk * 32 + a_byt);
    __syncthreads();

    auto load_blk = [&](int kb, int p) {
#pragma unroll
        for (int j = 0; j < 4; j++) {
            int slot = tid + j * 128;
            int r = slot >> 3, c8 = (slot & 7) * 8;
            const __half* kg = K + base + (size_t)(kb * 64 + r) * D_MODEL + c8;
            const __half* vg = V + base + (size_t)(kb * 64 + r) * D_MODEL + c8;
            cp_async16(&Ks[p * 64 * AKP + r * AKP + c8], kg);
            cp_async16(&Vs[p * 64 * AKP + r * AKP + c8], vg);
        }
        cp_commit();
    };
    load_blk(0, 0);
    load_blk(1, 1);

    float m[2][2], l[2][2];
    float oacc[2][8][4];
#pragma unroll
    for (int mt = 0; mt < 2; mt++) {
        m[mt][0] = -INFINITY; m[mt][1] = -INFINITY;
        l[mt][0] = 0.0f; l[mt][1] = 0.0f;
#pragma unroll
        for (int nt = 0; nt < 8; nt++)
#pragma unroll
            for (int i = 0; i < 4; i++) oacc[mt][nt][i] = 0.0f;
    }

    const int NB = SEQ / 64;  // 32
    for (int kb = 0; kb < NB; kb++) {
        const int p = kb % NSTG;
        if (kb < NB - 1) cp_wait<1>(); else cp_wait<0>();
        __syncthreads();
        if (kb + 2 < NB) load_blk(kb + 2, (kb + 2) % NSTG);

        // S = Q @ K^T (base-2 domain)
        float s[2][8][4];
#pragma unroll
        for (int mt = 0; mt < 2; mt++)
#pragma unroll
            for (int nt = 0; nt < 8; nt++)
#pragma unroll
                for (int i = 0; i < 4; i++) s[mt][nt][i] = 0.0f;

        const uint32_t kBase = sK + p * (64 * AKP * 2);
#pragma unroll
        for (int kk = 0; kk < 4; kk++) {
#pragma unroll
            for (int nt2 = 0; nt2 < 4; nt2++) {
                uint32_t ub[4];
                ldsm4(ub, kBase + (nt2 * 16 + b_row) * (AKP * 2) + kk * 32 + b_byt);
#pragma unroll
                for (int mt = 0; mt < 2; mt++) {
                    mma16(s[mt][nt2 * 2],     qa[mt][kk][0], qa[mt][kk][1], qa[mt][kk][2], qa[mt][kk][3], ub[0], ub[1]);
                    mma16(s[mt][nt2 * 2 + 1], qa[mt][kk][0], qa[mt][kk][1], qa[mt][kk][2], qa[mt][kk][3], ub[2], ub[3]);
                }
            }
        }

        // Online softmax with warp-voted rescale skip.
        uint32_t ph0[2][8], ph1[2][8];
#pragma unroll
        for (int mt = 0; mt < 2; mt++) {
            float rmax0 = -INFINITY, rmax1 = -INFINITY;
#pragma unroll
            for (int nt = 0; nt < 8; nt++) {
                rmax0 = fmaxf(rmax0, fmaxf(s[mt][nt][0], s[mt][nt][1]));
                rmax1 = fmaxf(rmax1, fmaxf(s[mt][nt][2], s[mt][nt][3]));
            }
            rmax0 = fmaxf(rmax0, __shfl_xor_sync(0xffffffffu, rmax0, 1));
            rmax0 = fmaxf(rmax0, __shfl_xor_sync(0xffffffffu, rmax0, 2));
            rmax1 = fmaxf(rmax1, __shfl_xor_sync(0xffffffffu, rmax1, 1));
            rmax1 = fmaxf(rmax1, __shfl_xor_sync(0xffffffffu, rmax1, 2));

            const bool upd = (rmax0 > m[mt][0]) || (rmax1 > m[mt][1]);
            if (__any_sync(0xffffffffu, upd)) {
                const float mn0 = fmaxf(m[mt][0], rmax0);
                const float mn1 = fmaxf(m[mt][1], rmax1);
                const float alpha0 = exp2f(m[mt][0] - mn0);
                const float alpha1 = exp2f(m[mt][1] - mn1);
                l[mt][0] *= alpha0;
                l[mt][1] *= alpha1;
                m[mt][0] = mn0; m[mt][1] = mn1;
#pragma unroll
                for (int nt = 0; nt < 8; nt++) {
                    oacc[mt][nt][0] *= alpha0; oacc[mt][nt][1] *= alpha0;
                    oacc[mt][nt][2] *= alpha1; oacc[mt][nt][3] *= alpha1;
                }
            }

            const float mn0 = m[mt][0], mn1 = m[mt][1];
            float rs0 = 0.0f, rs1 = 0.0f;
#pragma unroll
            for (int nt = 0; nt < 8; nt++) {
                ph0[mt][nt] = ex2h2(packh2(s[mt][nt][0] - mn0, s[mt][nt][1] - mn0));
                ph1[mt][nt] = ex2h2(packh2(s[mt][nt][2] - mn1, s[mt][nt][3] - mn1));
                float2 f0 = __half22float2(*(__half2*)&ph0[mt][nt]);
                float2 f1 = __half22float2(*(__half2*)&ph1[mt][nt]);
                rs0 += f0.x + f0.y;
                rs1 += f1.x + f1.y;
            }
            rs0 += __shfl_xor_sync(0xffffffffu, rs0, 1);
            rs0 += __shfl_xor_sync(0xffffffffu, rs0, 2);
            rs1 += __shfl_xor_sync(0xffffffffu, rs1, 1);
            rs1 += __shfl_xor_sync(0xffffffffu, rs1, 2);

            l[mt][0] += rs0;
            l[mt][1] += rs1;
        }

        // PV: A-frags = ph (fp16 already); V B-frags ldsm.trans shared over mt.
        const uint32_t vBase = sV + p * (64 * AKP * 2);
#pragma unroll
        for (int kk = 0; kk < 4; kk++) {
#pragma unroll
            for (int nt2 = 0; nt2 < 4; nt2++) {
                uint32_t ub[4];
                ldsm4t(ub, vBase + (kk * 16 + v_row) * (AKP * 2) + nt2 * 32 + v_byt);
#pragma unroll
                for (int mt = 0; mt < 2; mt++) {
                    mma16(oacc[mt][nt2 * 2],     ph0[mt][2 * kk], ph1[mt][2 * kk],
                          ph0[mt][2 * kk + 1], ph1[mt][2 * kk + 1], ub[0], ub[1]);
                    mma16(oacc[mt][nt2 * 2 + 1], ph0[mt][2 * kk], ph1[mt][2 * kk],
                          ph0[mt][2 * kk + 1], ph1[mt][2 * kk + 1], ub[2], ub[3]);
                }
            }
        }
    }

#pragma unroll
    for (int mt = 0; mt < 2; mt++) {
        const float inv0 = 1.0f / l[mt][0];
        const float inv1 = 1.0f / l[mt][1];
#pragma unroll
        for (int nt = 0; nt < 8; nt++) {
            const int col = nt * 8 + 2 * tig;
            __half* o0 = O + base + (size_t)(q0 + qb + mt * 16 + g) * D_MODEL + col;
            __half* o1 = O + base + (size_t)(q0 + qb + mt * 16 + g + 8) * D_MODEL + col;
            *(__half2*)o0 = __floats2half2_rn(oacc[mt][nt][0] * inv0, oacc[mt][nt][1] * inv0);
            *(__half2*)o1 = __floats2half2_rn(oacc[mt][nt][2] * inv1, oacc[mt][nt][3] * inv1);
        }
    }
}

// ---------------------------------------------------------------------------
// Launch
// ---------------------------------------------------------------------------
extern "C" void kernel_launch(void* const* d_in, const int* in_sizes, int n_in,
                              void* d_out, int out_size)
{
    const float* q  = (const float*)d_in[0];
    const float* k  = (const float*)d_in[1];
    const float* v  = (const float*)d_in[2];
    const float* Wq = (const float*)d_in[3];
    const float* bq = (const float*)d_in[4];
    const float* Wk = (const float*)d_in[5];
    const float* bk = (const float*)d_in[6];
    const float* Wv = (const float*)d_in[7];
    const float* bv = (const float*)d_in[8];
    const float* Wo = (const float*)d_in[9];
    const float* bo = (const float*)d_in[10];
    float* out = (float*)d_out;

    __half *pqh, *pkh, *pvh, *pQh, *pKh, *pVh, *pOh, *pWh;
    cudaGetSymbolAddress((void**)&pqh, g_qh);
    cudaGetSymbolAddress((void**)&pkh, g_kh);
    cudaGetSymbolAddress((void**)&pvh, g_vh);
    cudaGetSymbolAddress((void**)&pQh, g_Qh);
    cudaGetSymbolAddress((void**)&pKh, g_Kh);
    cudaGetSymbolAddress((void**)&pVh, g_Vh);
    cudaGetSymbolAddress((void**)&pOh, g_Oh);
    cudaGetSymbolAddress((void**)&pWh, g_Wh);

    cudaFuncSetAttribute(gemm_qkv, cudaFuncAttributeMaxDynamicSharedMemorySize,
                         GEMM_SMEM);
    cudaFuncSetAttribute(gemm_o, cudaFuncAttributeMaxDynamicSharedMemorySize,
                         GEMM_SMEM);
    cudaFuncSetAttribute(attn_h, cudaFuncAttributeMaxDynamicSharedMemorySize,
                         ATTN_SMEM);

    const int WN = D_MODEL * D_MODEL;
    const int XN = MTOT * D_MODEL;
    dim3 gX(XN / 2048, 3);
    cvt3_f2h<<<gX, 256>>>(q, k, v, pqh, pkh, pvh);
    dim3 gW(WN / 2048, 4);
    cvt4_f2h<<<gW, 256>>>(Wq, Wk, Wv, Wo, pWh);

    dim3 gQKV(D_MODEL / 128, MTOT / 128, 3);  // (8, 64, 3)
    gemm_qkv<<<gQKV, 128, GEMM_SMEM>>>(pqh, pkh, pvh, pWh,
                                       bq, bk, bv, pQh, pKh, pVh);

    dim3 gAttn(SEQ / 128, BATCH * NUM_HEADS);  // (16, 64)
    attn_h<<<gAttn, 128, ATTN_SMEM>>>(pQh, pKh, pVh, pOh);

    dim3 gGemm(D_MODEL / 128, MTOT / 128);  // (8, 64)
    gemm_o<<<gGemm, 128, GEMM_SMEM>>>(pOh, pWh + 3 * (size_t)WN, bo, out);
}

// round 13
// speedup vs baseline: 1.0272x; 1.0272x over previous
#include <cuda_runtime.h>
#include <cuda_fp16.h>
#include <math.h>
#include <stdint.h>

#define D_MODEL 1024
#define NUM_HEADS 16
#define DK 64
#define BATCH 4
#define SEQ 2048
#define MTOT (BATCH * SEQ)   // 8192

// Scratch (no allocation allowed) — fp16 intermediates
__device__ __half g_qh[MTOT * D_MODEL];
__device__ __half g_kh[MTOT * D_MODEL];
__device__ __half g_vh[MTOT * D_MODEL];
__device__ __half g_Qh[MTOT * D_MODEL];
__device__ __half g_Kh[MTOT * D_MODEL];
__device__ __half g_Vh[MTOT * D_MODEL];
__device__ __half g_Oh[MTOT * D_MODEL];
__device__ __half g_Wh[4 * D_MODEL * D_MODEL];

// ---------------------------------------------------------------------------
// Helpers
// ---------------------------------------------------------------------------
__device__ __forceinline__ uint32_t packh2(float a, float b) {
    __half2 h = __floats2half2_rn(a, b);
    return *reinterpret_cast<uint32_t*>(&h);
}
__device__ __forceinline__ uint32_t ex2h2(uint32_t x) {
    uint32_t r;
    asm("ex2.approx.f16x2 %0, %1;" : "=r"(r) : "r"(x));
    return r;
}

__device__ __forceinline__ void mma16(float c[4], uint32_t a0, uint32_t a1,
                                      uint32_t a2, uint32_t a3,
                                      uint32_t b0, uint32_t b1) {
    asm volatile(
        "mma.sync.aligned.m16n8k16.row.col.f32.f16.f16.f32 "
        "{%0,%1,%2,%3}, {%4,%5,%6,%7}, {%8,%9}, {%0,%1,%2,%3};"
        : "+f"(c[0]), "+f"(c[1]), "+f"(c[2]), "+f"(c[3])
        : "r"(a0), "r"(a1), "r"(a2), "r"(a3), "r"(b0), "r"(b1));
}

__device__ __forceinline__ void ldsm4(uint32_t r[4], uint32_t saddr) {
    asm volatile(
        "ldmatrix.sync.aligned.m8n8.x4.shared.b16 {%0,%1,%2,%3}, [%4];"
        : "=r"(r[0]), "=r"(r[1]), "=r"(r[2]), "=r"(r[3]) : "r"(saddr));
}
__device__ __forceinline__ void ldsm4t(uint32_t r[4], uint32_t saddr) {
    asm volatile(
        "ldmatrix.sync.aligned.m8n8.x4.trans.shared.b16 {%0,%1,%2,%3}, [%4];"
        : "=r"(r[0]), "=r"(r[1]), "=r"(r[2]), "=r"(r[3]) : "r"(saddr));
}

__device__ __forceinline__ void cp_async16(void* smem, const void* gmem) {
    uint32_t s = (uint32_t)__cvta_generic_to_shared(smem);
    asm volatile("cp.async.cg.shared.global [%0], [%1], 16;" :: "r"(s), "l"(gmem));
}
__device__ __forceinline__ void cp_commit() {
    asm volatile("cp.async.commit_group;");
}
template <int N>
__device__ __forceinline__ void cp_wait() {
    asm volatile("cp.async.wait_group %0;" :: "n"(N));
}

// ---------------------------------------------------------------------------
// Fused fp32->fp16 conversions
// ---------------------------------------------------------------------------
__global__ __launch_bounds__(256) void cvt3_f2h(
    const float* __restrict__ s0, const float* __restrict__ s1,
    const float* __restrict__ s2,
    __half* __restrict__ d0, __half* __restrict__ d1, __half* __restrict__ d2)
{
    const float* src = (blockIdx.y == 0) ? s0 : (blockIdx.y == 1) ? s1 : s2;
    __half* dst = (blockIdx.y == 0) ? d0 : (blockIdx.y == 1) ? d1 : d2;
    int i = (blockIdx.x * 256 + threadIdx.x) * 8;
    float4 v0 = *(const float4*)(src + i);
    float4 v1 = *(const float4*)(src + i + 4);
    __half2 h[4];
    h[0] = __floats2half2_rn(v0.x, v0.y);
    h[1] = __floats2half2_rn(v0.z, v0.w);
    h[2] = __floats2half2_rn(v1.x, v1.y);
    h[3] = __floats2half2_rn(v1.z, v1.w);
    *(uint4*)(dst + i) = *(uint4*)h;
}

__global__ __launch_bounds__(256) void cvt4_f2h(
    const float* __restrict__ s0, const float* __restrict__ s1,
    const float* __restrict__ s2, const float* __restrict__ s3,
    __half* __restrict__ dst)
{
    const float* src = (blockIdx.y == 0) ? s0 : (blockIdx.y == 1) ? s1
                       : (blockIdx.y == 2) ? s2 : s3;
    __half* d = dst + (size_t)blockIdx.y * D_MODEL * D_MODEL;
    int i = (blockIdx.x * 256 + threadIdx.x) * 8;
    float4 v0 = *(const float4*)(src + i);
    float4 v1 = *(const float4*)(src + i + 4);
    __half2 h[4];
    h[0] = __floats2half2_rn(v0.x, v0.y);
    h[1] = __floats2half2_rn(v0.z, v0.w);
    h[2] = __floats2half2_rn(v1.x, v1.y);
    h[3] = __floats2half2_rn(v1.z, v1.w);
    *(uint4*)(d + i) = *(uint4*)h;
}

// ---------------------------------------------------------------------------
// fp16 GEMM v4: 128 thr, 4 warps (2x2), warp 64x64, BK=64 halves, 3-stage
// cp.async ring -> 16 syncthreads instead of 32. Pitch 72 halves (144B rows,
// ldsm conflict-free: row stride 36 banks == 4 mod 32).
// ---------------------------------------------------------------------------
#define HP 72
#define GSTG 3
#define GSTAGE (128 * HP)
#define GEMM_SMEM (GSTG * 2 * GSTAGE * 2)  // 110592 B

template <int OUT_HALF>
__device__ __forceinline__ void gemm_body(
    const __half* __restrict__ A, const __half* __restrict__ W,
    const float* __restrict__ bias, void* __restrict__ Cout)
{
    extern __shared__ __align__(16) __half sgh[];
    __half* As = sgh;
    __half* Ws = sgh + GSTG * GSTAGE;

    const int tid = threadIdx.x;
    const int lane = tid & 31;
    const int g = lane >> 2, tig = lane & 3;
    const int wid = tid >> 5;
    const int wm = wid & 1;
    const int wn = wid >> 1;
    const int row0 = blockIdx.y * 128;
    const int col0 = blockIdx.x * 128;

    const __half* Ag = A + (size_t)row0 * D_MODEL;
    const __half* Wg = W + (size_t)col0 * D_MODEL;

    const uint32_t sA = (uint32_t)__cvta_generic_to_shared(As);
    const uint32_t sW = (uint32_t)__cvta_generic_to_shared(Ws);

    // stage: 128 rows x 64 halves (128B) per matrix = 1024 x 16B chunks each
    auto load_stage = [&](int ch, int st) {
        const int kof = ch * 64;
#pragma unroll
        for (int j = 0; j < 8; j++) {
            int slot = tid + j * 128;
            int r = slot >> 3, c = (slot & 7) * 8;
            cp_async16(&As[st * GSTAGE + r * HP + c],
                       Ag + (size_t)r * D_MODEL + kof + c);
            cp_async16(&Ws[st * GSTAGE + r * HP + c],
                       Wg + (size_t)r * D_MODEL + kof + c);
        }
        cp_commit();
    };
    load_stage(0, 0);
    load_stage(1, 1);

    float acc[4][8][4];
#pragma unroll
    for (int mt = 0; mt < 4; mt++)
#pragma unroll
        for (int nt = 0; nt < 8; nt++)
#pragma unroll
            for (int i = 0; i < 4; i++) acc[mt][nt][i] = 0.0f;

    const int a_row = lane & 15;
    const int a_byt = (lane >> 4) << 4;
    const int b_row = (lane & 7) + ((lane >> 4) << 3);
    const int b_byt = ((lane >> 3) & 1) << 4;

    const int NCH = D_MODEL / 64;  // 16
    for (int ch = 0; ch < NCH; ch++) {
        const int p = ch % GSTG;
        if (ch < NCH - 1) cp_wait<1>();
        else cp_wait<0>();
        __syncthreads();
        if (ch + 2 < NCH) load_stage(ch + 2, (ch + 2) % GSTG);

        const uint32_t aBase = sA + p * (GSTAGE * 2);
        const uint32_t wBase = sW + p * (GSTAGE * 2);
#pragma unroll
        for (int kk = 0; kk < 4; kk++) {
            uint32_t ua[4][4];
#pragma unroll
            for (int mt = 0; mt < 4; mt++)
                ldsm4(ua[mt], aBase + (wm * 64 + mt * 16 + a_row) * (HP * 2)
                              + kk * 32 + a_byt);
#pragma unroll
            for (int nt2 = 0; nt2 < 4; nt2++) {
                uint32_t ub[4];
                ldsm4(ub, wBase + (wn * 64 + nt2 * 16 + b_row) * (HP * 2)
                          + kk * 32 + b_byt);
#pragma unroll
                for (int mt = 0; mt < 4; mt++) {
                    mma16(acc[mt][nt2 * 2],     ua[mt][0], ua[mt][1], ua[mt][2], ua[mt][3], ub[0], ub[1]);
                    mma16(acc[mt][nt2 * 2 + 1], ua[mt][0], ua[mt][1], ua[mt][2], ua[mt][3], ub[2], ub[3]);
                }
            }
        }
    }

#pragma unroll
    for (int mt = 0; mt < 4; mt++) {
        const int ra = row0 + wm * 64 + mt * 16 + g;
#pragma unroll
        for (int nt = 0; nt < 8; nt++) {
            const int col = col0 + wn * 64 + nt * 8 + 2 * tig;
            const float bz0 = bias[col], bz1 = bias[col + 1];
            float v0 = acc[mt][nt][0] + bz0, v1 = acc[mt][nt][1] + bz1;
            float v2 = acc[mt][nt][2] + bz0, v3 = acc[mt][nt][3] + bz1;
            if (OUT_HALF) {
                __half* C = (__half*)Cout;
                *(__half2*)(C + (size_t)ra * D_MODEL + col) = __floats2half2_rn(v0, v1);
                *(__half2*)(C + (size_t)(ra + 8) * D_MODEL + col) = __floats2half2_rn(v2, v3);
            } else {
                float* C = (float*)Cout;
                *(float2*)(C + (size_t)ra * D_MODEL + col) = make_float2(v0, v1);
                *(float2*)(C + (size_t)(ra + 8) * D_MODEL + col) = make_float2(v2, v3);
            }
        }
    }
}

// Fused Q/K/V projections: blockIdx.z selects (input, weight, bias, output).
__global__ __launch_bounds__(128, 2) void gemm_qkv(
    const __half* __restrict__ a0, const __half* __restrict__ a1,
    const __half* __restrict__ a2, const __half* __restrict__ Wall,
    const float* __restrict__ b0, const float* __restrict__ b1,
    const float* __restrict__ b2,
    __half* __restrict__ c0, __half* __restrict__ c1, __half* __restrict__ c2)
{
    const int z = blockIdx.z;
    const __half* A = (z == 0) ? a0 : (z == 1) ? a1 : a2;
    const float* bias = (z == 0) ? b0 : (z == 1) ? b1 : b2;
    __half* C = (z == 0) ? c0 : (z == 1) ? c1 : c2;
    gemm_body<1>(A, Wall + (size_t)z * D_MODEL * D_MODEL, bias, C);
}

// O projection (fp32 out)
__global__ __launch_bounds__(128, 2) void gemm_o(
    const __half* __restrict__ A, const __half* __restrict__ W,
    const float* __restrict__ bias, float* __restrict__ C)
{
    gemm_body<0>(A, W, bias, C);
}

// ---------------------------------------------------------------------------
// fp16 flash attention (round-10 version, byte-exact): 128 threads, 4 warps x
// 32 q-rows, Bc=64, base-2 ex2 softmax, 3-stage K/V ring, single sync/iter.
// ---------------------------------------------------------------------------
#define AKP 72
#define NSTG 3
#define ATTN_SMEM (2 * NSTG * 64 * AKP * 2)  // 55296 B

__global__ __launch_bounds__(128, 2) void attn_h(
    const __half* __restrict__ Q, const __half* __restrict__ K,
    const __half* __restrict__ V, __half* __restrict__ O)
{
    extern __shared__ __align__(16) __half smh[];
    __half* Ks = smh;
    __half* Vs = smh + NSTG * 64 * AKP;
    __half* Qst = smh;                       // overlay

    const int tid = threadIdx.x;
    const int lane = tid & 31;
    const int g = lane >> 2, tig = lane & 3;
    const int wid = tid >> 5;
    const int qb = wid * 32;                 // warp covers 32 q-rows

    const int b = blockIdx.y >> 4;
    const int h = blockIdx.y & 15;
    const int q0 = blockIdx.x * 128;
    const size_t base = (size_t)b * SEQ * D_MODEL + (size_t)h * DK;

    // Stage Q scaled by 0.125*log2(e) -> base-2 scores out of the MMA.
    {
        const __half2 sc = __half2half2(__float2half(0.18033688f));
        for (int i = tid; i < 128 * 8; i += 128) {
            int r = i >> 3, c8 = (i & 7) * 8;
            uint4 raw = *(const uint4*)(Q + base + (size_t)(q0 + r) * D_MODEL + c8);
            __half2* hp = (__half2*)&raw;
            hp[0] = __hmul2(hp[0], sc); hp[1] = __hmul2(hp[1], sc);
            hp[2] = __hmul2(hp[2], sc); hp[3] = __hmul2(hp[3], sc);
            *(uint4*)&Qst[r * AKP + c8] = raw;
        }
    }
    __syncthreads();

    const uint32_t sQ = (uint32_t)__cvta_generic_to_shared(Qst);
    const uint32_t sK = (uint32_t)__cvta_generic_to_shared(Ks);
    const uint32_t sV = (uint32_t)__cvta_generic_to_shared(Vs);
    const int a_row = lane & 15;
    const int a_byt = (lane >> 4) << 4;
    const int b_row = (lane & 7) + ((lane >> 4) << 3);
    const int b_byt = ((lane >> 3) & 1) << 4;
    const int v_row = (lane & 7) + (((lane >> 3) & 1) << 3);
    const int v_byt = (lane >> 4) << 4;

    uint32_t qa[2][4][4];
#pragma unroll
    for (int mt = 0; mt < 2; mt++)
#pragma unroll
        for (int kk = 0; kk < 4; kk++)
            ldsm4(qa[mt][kk], sQ + (qb + mt * 16 + a_row) * (AKP * 2) + kk * 32 + a_byt);
    __syncthreads();

    auto load_blk = [&](int kb, int p) {
#pragma unroll
        for (int j = 0; j < 4; j++) {
            int slot = tid + j * 128;
            int r = slot >> 3, c8 = (slot & 7) * 8;
            const __half* kg = K + base + (size_t)(kb * 64 + r) * D_MODEL + c8;
            const __half* vg = V + base + (size_t)(kb * 64 + r) * D_MODEL + c8;
            cp_async16(&Ks[p * 64 * AKP + r * AKP + c8], kg);
            cp_async16(&Vs[p * 64 * AKP + r * AKP + c8], vg);
        }
        cp_commit();
    };
    load_blk(0, 0);
    load_blk(1, 1);

    float m[2][2], l[2][2];
    float oacc[2][8][4];
#pragma unroll
    for (int mt = 0; mt < 2; mt++) {
        m[mt][0] = -INFINITY; m[mt][1] = -INFINITY;
        l[mt][0] = 0.0f; l[mt][1] = 0.0f;
#pragma unroll
        for (int nt = 0; nt < 8; nt++)
#pragma unroll
            for (int i = 0; i < 4; i++) oacc[mt][nt][i] = 0.0f;
    }

    const int NB = SEQ / 64;  // 32
    for (int kb = 0; kb < NB; kb++) {
        const int p = kb % NSTG;
        if (kb < NB - 1) cp_wait<1>(); else cp_wait<0>();
        __syncthreads();
        if (kb + 2 < NB) load_blk(kb + 2, (kb + 2) % NSTG);

        // S = Q @ K^T (base-2 domain)
        float s[2][8][4];
#pragma unroll
        for (int mt = 0; mt < 2; mt++)
#pragma unroll
            for (int nt = 0; nt < 8; nt++)
#pragma unroll
                for (int i = 0; i < 4; i++) s[mt][nt][i] = 0.0f;

        const uint32_t kBase = sK + p * (64 * AKP * 2);
#pragma unroll
        for (int kk = 0; kk < 4; kk++) {
#pragma unroll
            for (int nt2 = 0; nt2 < 4; nt2++) {
                uint32_t ub[4];
                ldsm4(ub, kBase + (nt2 * 16 + b_row) * (AKP * 2) + kk * 32 + b_byt);
#pragma unroll
                for (int mt = 0; mt < 2; mt++) {
                    mma16(s[mt][nt2 * 2],     qa[mt][kk][0], qa[mt][kk][1], qa[mt][kk][2], qa[mt][kk][3], ub[0], ub[1]);
                    mma16(s[mt][nt2 * 2 + 1], qa[mt][kk][0], qa[mt][kk][1], qa[mt][kk][2], qa[mt][kk][3], ub[2], ub[3]);
                }
            }
        }

        // Online softmax per m-fragment
        uint32_t ph0[2][8], ph1[2][8];
#pragma unroll
        for (int mt = 0; mt < 2; mt++) {
            float rmax0 = -INFINITY, rmax1 = -INFINITY;
#pragma unroll
            for (int nt = 0; nt < 8; nt++) {
                rmax0 = fmaxf(rmax0, fmaxf(s[mt][nt][0], s[mt][nt][1]));
                rmax1 = fmaxf(rmax1, fmaxf(s[mt][nt][2], s[mt][nt][3]));
            }
            rmax0 = fmaxf(rmax0, __shfl_xor_sync(0xffffffffu, rmax0, 1));
            rmax0 = fmaxf(rmax0, __shfl_xor_sync(0xffffffffu, rmax0, 2));
            rmax1 = fmaxf(rmax1, __shfl_xor_sync(0xffffffffu, rmax1, 1));
            rmax1 = fmaxf(rmax1, __shfl_xor_sync(0xffffffffu, rmax1, 2));

            const float mn0 = fmaxf(m[mt][0], rmax0);
            const float mn1 = fmaxf(m[mt][1], rmax1);
            const float alpha0 = exp2f(m[mt][0] - mn0);
            const float alpha1 = exp2f(m[mt][1] - mn1);

            float rs0 = 0.0f, rs1 = 0.0f;
#pragma unroll
            for (int nt = 0; nt < 8; nt++) {
                ph0[mt][nt] = ex2h2(packh2(s[mt][nt][0] - mn0, s[mt][nt][1] - mn0));
                ph1[mt][nt] = ex2h2(packh2(s[mt][nt][2] - mn1, s[mt][nt][3] - mn1));
                float2 f0 = __half22float2(*(__half2*)&ph0[mt][nt]);
                float2 f1 = __half22float2(*(__half2*)&ph1[mt][nt]);
                rs0 += f0.x + f0.y;
                rs1 += f1.x + f1.y;
            }
            rs0 += __shfl_xor_sync(0xffffffffu, rs0, 1);
            rs0 += __shfl_xor_sync(0xffffffffu, rs0, 2);
            rs1 += __shfl_xor_sync(0xffffffffu, rs1, 1);
            rs1 += __shfl_xor_sync(0xffffffffu, rs1, 2);

            l[mt][0] = l[mt][0] * alpha0 + rs0;
            l[mt][1] = l[mt][1] * alpha1 + rs1;
            m[mt][0] = mn0; m[mt][1] = mn1;
#pragma unroll
            for (int nt = 0; nt < 8; nt++) {
                oacc[mt][nt][0] *= alpha0; oacc[mt][nt][1] *= alpha0;
                oacc[mt][nt][2] *= alpha1; oacc[mt][nt][3] *= alpha1;
            }
        }

        // PV: A-frags = ph (fp16 already); V B-frags ldsm.trans shared over mt.
        const uint32_t vBase = sV + p * (64 * AKP * 2);
#pragma unroll
        for (int kk = 0; kk < 4; kk++) {
#pragma unroll
            for (int nt2 = 0; nt2 < 4; nt2++) {
                uint32_t ub[4];
                ldsm4t(ub, vBase + (kk * 16 + v_row) * (AKP * 2) + nt2 * 32 + v_byt);
#pragma unroll
                for (int mt = 0; mt < 2; mt++) {
                    mma16(oacc[mt][nt2 * 2],     ph0[mt][2 * kk], ph1[mt][2 * kk],
                          ph0[mt][2 * kk + 1], ph1[mt][2 * kk + 1], ub[0], ub[1]);
                    mma16(oacc[mt][nt2 * 2 + 1], ph0[mt][2 * kk], ph1[mt][2 * kk],
                          ph0[mt][2 * kk + 1], ph1[mt][2 * kk + 1], ub[2], ub[3]);
                }
            }
        }
    }

#pragma unroll
    for (int mt = 0; mt < 2; mt++) {
        const float inv0 = 1.0f / l[mt][0];
        const float inv1 = 1.0f / l[mt][1];
#pragma unroll
        for (int nt = 0; nt < 8; nt++) {
            const int col = nt * 8 + 2 * tig;
            __half* o0 = O + base + (size_t)(q0 + qb + mt * 16 + g) * D_MODEL + col;
            __half* o1 = O + base + (size_t)(q0 + qb + mt * 16 + g + 8) * D_MODEL + col;
            *(__half2*)o0 = __floats2half2_rn(oacc[mt][nt][0] * inv0, oacc[mt][nt][1] * inv0);
            *(__half2*)o1 = __floats2half2_rn(oacc[mt][nt][2] * inv1, oacc[mt][nt][3] * inv1);
        }
    }
}

// ---------------------------------------------------------------------------
// Launch
// ---------------------------------------------------------------------------
extern "C" void kernel_launch(void* const* d_in, const int* in_sizes, int n_in,
                              void* d_out, int out_size)
{
    const float* q  = (const float*)d_in[0];
    const float* k  = (const float*)d_in[1];
    const float* v  = (const float*)d_in[2];
    const float* Wq = (const float*)d_in[3];
    const float* bq = (const float*)d_in[4];
    const float* Wk = (const float*)d_in[5];
    const float* bk = (const float*)d_in[6];
    const float* Wv = (const float*)d_in[7];
    const float* bv = (const float*)d_in[8];
    const float* Wo = (const float*)d_in[9];
    const float* bo = (const float*)d_in[10];
    float* out = (float*)d_out;

    __half *pqh, *pkh, *pvh, *pQh, *pKh, *pVh, *pOh, *pWh;
    cudaGetSymbolAddress((void**)&pqh, g_qh);
    cudaGetSymbolAddress((void**)&pkh, g_kh);
    cudaGetSymbolAddress((void**)&pvh, g_vh);
    cudaGetSymbolAddress((void**)&pQh, g_Qh);
    cudaGetSymbolAddress((void**)&pKh, g_Kh);
    cudaGetSymbolAddress((void**)&pVh, g_Vh);
    cudaGetSymbolAddress((void**)&pOh, g_Oh);
    cudaGetSymbolAddress((void**)&pWh, g_Wh);

    cudaFuncSetAttribute(gemm_qkv, cudaFuncAttributeMaxDynamicSharedMemorySize,
                         GEMM_SMEM);
    cudaFuncSetAttribute(gemm_o, cudaFuncAttributeMaxDynamicSharedMemorySize,
                         GEMM_SMEM);
    cudaFuncSetAttribute(attn_h, cudaFuncAttributeMaxDynamicSharedMemorySize,
                         ATTN_SMEM);

    const int WN = D_MODEL * D_MODEL;
    const int XN = MTOT * D_MODEL;
    dim3 gX(XN / 2048, 3);
    cvt3_f2h<<<gX, 256>>>(q, k, v, pqh, pkh, pvh);
    dim3 gW(WN / 2048, 4);
    cvt4_f2h<<<gW, 256>>>(Wq, Wk, Wv, Wo, pWh);

    dim3 gQKV(D_MODEL / 128, MTOT / 128, 3);  // (8, 64, 3)
    gemm_qkv<<<gQKV, 128, GEMM_SMEM>>>(pqh, pkh, pvh, pWh,
                                       bq, bk, bv, pQh, pKh, pVh);

    dim3 gAttn(SEQ / 128, BATCH * NUM_HEADS);  // (16, 64)
    attn_h<<<gAttn, 128, ATTN_SMEM>>>(pQh, pKh, pVh, pOh);

    dim3 gGemm(D_MODEL / 128, MTOT / 128);  // (8, 64)
    gemm_o<<<gGemm, 128, GEMM_SMEM>>>(pOh, pWh + 3 * (size_t)WN, bo, out);
}

// round 15
// speedup vs baseline: 1.0305x; 1.0031x over previous
#include <cuda_runtime.h>
#include <cuda_fp16.h>
#include <math.h>
#include <stdint.h>

#define D_MODEL 1024
#define NUM_HEADS 16
#define DK 64
#define BATCH 4
#define SEQ 2048
#define MTOT (BATCH * SEQ)   // 8192

// Scratch (no allocation allowed) — fp16 intermediates
__device__ __half g_qh[MTOT * D_MODEL];
__device__ __half g_kh[MTOT * D_MODEL];
__device__ __half g_vh[MTOT * D_MODEL];
__device__ __half g_Qh[MTOT * D_MODEL];
__device__ __half g_Kh[MTOT * D_MODEL];
__device__ __half g_Vh[MTOT * D_MODEL];
__device__ __half g_Oh[MTOT * D_MODEL];
__device__ __half g_Wh[4 * D_MODEL * D_MODEL];

// ---------------------------------------------------------------------------
// Helpers
// ---------------------------------------------------------------------------
__device__ __forceinline__ uint32_t packh2(float a, float b) {
    __half2 h = __floats2half2_rn(a, b);
    return *reinterpret_cast<uint32_t*>(&h);
}
__device__ __forceinline__ uint32_t ex2h2(uint32_t x) {
    uint32_t r;
    asm("ex2.approx.f16x2 %0, %1;" : "=r"(r) : "r"(x));
    return r;
}

__device__ __forceinline__ void mma16(float c[4], uint32_t a0, uint32_t a1,
                                      uint32_t a2, uint32_t a3,
                                      uint32_t b0, uint32_t b1) {
    asm volatile(
        "mma.sync.aligned.m16n8k16.row.col.f32.f16.f16.f32 "
        "{%0,%1,%2,%3}, {%4,%5,%6,%7}, {%8,%9}, {%0,%1,%2,%3};"
        : "+f"(c[0]), "+f"(c[1]), "+f"(c[2]), "+f"(c[3])
        : "r"(a0), "r"(a1), "r"(a2), "r"(a3), "r"(b0), "r"(b1));
}

__device__ __forceinline__ void ldsm4(uint32_t r[4], uint32_t saddr) {
    asm volatile(
        "ldmatrix.sync.aligned.m8n8.x4.shared.b16 {%0,%1,%2,%3}, [%4];"
        : "=r"(r[0]), "=r"(r[1]), "=r"(r[2]), "=r"(r[3]) : "r"(saddr));
}
__device__ __forceinline__ void ldsm4t(uint32_t r[4], uint32_t saddr) {
    asm volatile(
        "ldmatrix.sync.aligned.m8n8.x4.trans.shared.b16 {%0,%1,%2,%3}, [%4];"
        : "=r"(r[0]), "=r"(r[1]), "=r"(r[2]), "=r"(r[3]) : "r"(saddr));
}

__device__ __forceinline__ void cp_async16(void* smem, const void* gmem) {
    uint32_t s = (uint32_t)__cvta_generic_to_shared(smem);
    asm volatile("cp.async.cg.shared.global [%0], [%1], 16;" :: "r"(s), "l"(gmem));
}
__device__ __forceinline__ void cp_commit() {
    asm volatile("cp.async.commit_group;");
}
template <int N>
__device__ __forceinline__ void cp_wait() {
    asm volatile("cp.async.wait_group %0;" :: "n"(N));
}

// ---------------------------------------------------------------------------
// Fused fp32->fp16 conversions
// ---------------------------------------------------------------------------
__global__ __launch_bounds__(256) void cvt3_f2h(
    const float* __restrict__ s0, const float* __restrict__ s1,
    const float* __restrict__ s2,
    __half* __restrict__ d0, __half* __restrict__ d1, __half* __restrict__ d2)
{
    const float* src = (blockIdx.y == 0) ? s0 : (blockIdx.y == 1) ? s1 : s2;
    __half* dst = (blockIdx.y == 0) ? d0 : (blockIdx.y == 1) ? d1 : d2;
    int i = (blockIdx.x * 256 + threadIdx.x) * 8;
    float4 v0 = *(const float4*)(src + i);
    float4 v1 = *(const float4*)(src + i + 4);
    __half2 h[4];
    h[0] = __floats2half2_rn(v0.x, v0.y);
    h[1] = __floats2half2_rn(v0.z, v0.w);
    h[2] = __floats2half2_rn(v1.x, v1.y);
    h[3] = __floats2half2_rn(v1.z, v1.w);
    *(uint4*)(dst + i) = *(uint4*)h;
}

__global__ __launch_bounds__(256) void cvt4_f2h(
    const float* __restrict__ s0, const float* __restrict__ s1,
    const float* __restrict__ s2, const float* __restrict__ s3,
    __half* __restrict__ dst)
{
    const float* src = (blockIdx.y == 0) ? s0 : (blockIdx.y == 1) ? s1
                       : (blockIdx.y == 2) ? s2 : s3;
    __half* d = dst + (size_t)blockIdx.y * D_MODEL * D_MODEL;
    int i = (blockIdx.x * 256 + threadIdx.x) * 8;
    float4 v0 = *(const float4*)(src + i);
    float4 v1 = *(const float4*)(src + i + 4);
    __half2 h[4];
    h[0] = __floats2half2_rn(v0.x, v0.y);
    h[1] = __floats2half2_rn(v0.z, v0.w);
    h[2] = __floats2half2_rn(v1.x, v1.y);
    h[3] = __floats2half2_rn(v1.z, v1.w);
    *(uint4*)(d + i) = *(uint4*)h;
}

// ---------------------------------------------------------------------------
// fp16 GEMM (round-13): 128 thr, 4 warps (2x2), warp 64x64, BK=64 halves,
// 3-stage cp.async ring, pitch 72. OSCALE folds a scale into the epilogue
// before the fp16 RN (used by the Q projection to pre-scale for attention).
// ---------------------------------------------------------------------------
#define HP 72
#define GSTG 3
#define GSTAGE (128 * HP)
#define GEMM_SMEM (GSTG * 2 * GSTAGE * 2)  // 110592 B

template <int OUT_HALF>
__device__ __forceinline__ void gemm_body(
    const __half* __restrict__ A, const __half* __restrict__ W,
    const float* __restrict__ bias, void* __restrict__ Cout, float oscale)
{
    extern __shared__ __align__(16) __half sgh[];
    __half* As = sgh;
    __half* Ws = sgh + GSTG * GSTAGE;

    const int tid = threadIdx.x;
    const int lane = tid & 31;
    const int g = lane >> 2, tig = lane & 3;
    const int wid = tid >> 5;
    const int wm = wid & 1;
    const int wn = wid >> 1;
    const int row0 = blockIdx.y * 128;
    const int col0 = blockIdx.x * 128;

    const __half* Ag = A + (size_t)row0 * D_MODEL;
    const __half* Wg = W + (size_t)col0 * D_MODEL;

    const uint32_t sA = (uint32_t)__cvta_generic_to_shared(As);
    const uint32_t sW = (uint32_t)__cvta_generic_to_shared(Ws);

    auto load_stage = [&](int ch, int st) {
        const int kof = ch * 64;
#pragma unroll
        for (int j = 0; j < 8; j++) {
            int slot = tid + j * 128;
            int r = slot >> 3, c = (slot & 7) * 8;
            cp_async16(&As[st * GSTAGE + r * HP + c],
                       Ag + (size_t)r * D_MODEL + kof + c);
            cp_async16(&Ws[st * GSTAGE + r * HP + c],
                       Wg + (size_t)r * D_MODEL + kof + c);
        }
        cp_commit();
    };
    load_stage(0, 0);
    load_stage(1, 1);

    float acc[4][8][4];
#pragma unroll
    for (int mt = 0; mt < 4; mt++)
#pragma unroll
        for (int nt = 0; nt < 8; nt++)
#pragma unroll
            for (int i = 0; i < 4; i++) acc[mt][nt][i] = 0.0f;

    const int a_row = lane & 15;
    const int a_byt = (lane >> 4) << 4;
    const int b_row = (lane & 7) + ((lane >> 4) << 3);
    const int b_byt = ((lane >> 3) & 1) << 4;

    const int NCH = D_MODEL / 64;  // 16
    for (int ch = 0; ch < NCH; ch++) {
        const int p = ch % GSTG;
        if (ch < NCH - 1) cp_wait<1>();
        else cp_wait<0>();
        __syncthreads();
        if (ch + 2 < NCH) load_stage(ch + 2, (ch + 2) % GSTG);

        const uint32_t aBase = sA + p * (GSTAGE * 2);
        const uint32_t wBase = sW + p * (GSTAGE * 2);
#pragma unroll
        for (int kk = 0; kk < 4; kk++) {
            uint32_t ua[4][4];
#pragma unroll
            for (int mt = 0; mt < 4; mt++)
                ldsm4(ua[mt], aBase + (wm * 64 + mt * 16 + a_row) * (HP * 2)
                              + kk * 32 + a_byt);
#pragma unroll
            for (int nt2 = 0; nt2 < 4; nt2++) {
                uint32_t ub[4];
                ldsm4(ub, wBase + (wn * 64 + nt2 * 16 + b_row) * (HP * 2)
                          + kk * 32 + b_byt);
#pragma unroll
                for (int mt = 0; mt < 4; mt++) {
                    mma16(acc[mt][nt2 * 2],     ua[mt][0], ua[mt][1], ua[mt][2], ua[mt][3], ub[0], ub[1]);
                    mma16(acc[mt][nt2 * 2 + 1], ua[mt][0], ua[mt][1], ua[mt][2], ua[mt][3], ub[2], ub[3]);
                }
            }
        }
    }

#pragma unroll
    for (int mt = 0; mt < 4; mt++) {
        const int ra = row0 + wm * 64 + mt * 16 + g;
#pragma unroll
        for (int nt = 0; nt < 8; nt++) {
            const int col = col0 + wn * 64 + nt * 8 + 2 * tig;
            const float bz0 = bias[col], bz1 = bias[col + 1];
            float v0 = acc[mt][nt][0] + bz0, v1 = acc[mt][nt][1] + bz1;
            float v2 = acc[mt][nt][2] + bz0, v3 = acc[mt][nt][3] + bz1;
            if (OUT_HALF) {
                v0 *= oscale; v1 *= oscale; v2 *= oscale; v3 *= oscale;
                __half* C = (__half*)Cout;
                *(__half2*)(C + (size_t)ra * D_MODEL + col) = __floats2half2_rn(v0, v1);
                *(__half2*)(C + (size_t)(ra + 8) * D_MODEL + col) = __floats2half2_rn(v2, v3);
            } else {
                float* C = (float*)Cout;
                *(float2*)(C + (size_t)ra * D_MODEL + col) = make_float2(v0, v1);
                *(float2*)(C + (size_t)(ra + 8) * D_MODEL + col) = make_float2(v2, v3);
            }
        }
    }
}

// Fused Q/K/V projections: blockIdx.z selects (input, weight, bias, output).
// Q output (z==0) is pre-scaled by 0.125*log2(e) for base-2 attention scores.
__global__ __launch_bounds__(128, 2) void gemm_qkv(
    const __half* __restrict__ a0, const __half* __restrict__ a1,
    const __half* __restrict__ a2, const __half* __restrict__ Wall,
    const float* __restrict__ b0, const float* __restrict__ b1,
    const float* __restrict__ b2,
    __half* __restrict__ c0, __half* __restrict__ c1, __half* __restrict__ c2)
{
    const int z = blockIdx.z;
    const __half* A = (z == 0) ? a0 : (z == 1) ? a1 : a2;
    const float* bias = (z == 0) ? b0 : (z == 1) ? b1 : b2;
    __half* C = (z == 0) ? c0 : (z == 1) ? c1 : c2;
    const float sc = (z == 0) ? 0.18033688011112042f : 1.0f;
    gemm_body<1>(A, Wall + (size_t)z * D_MODEL * D_MODEL, bias, C, sc);
}

// O projection (fp32 out)
__global__ __launch_bounds__(128, 2) void gemm_o(
    const __half* __restrict__ A, const __half* __restrict__ W,
    const float* __restrict__ bias, float* __restrict__ C)
{
    gemm_body<0>(A, W, bias, C, 1.0f);
}

// ---------------------------------------------------------------------------
// fp16 flash attention (round-13 structure; Q already pre-scaled): 128 thr,
// 4 warps x 32 q-rows, Bc=64, base-2 ex2 softmax, 3-stage K/V ring,
// 1 sync/iter. S-MMA fp32 accumulate (numerics frozen).
// ---------------------------------------------------------------------------
#define AKP 72
#define NSTG 3
#define ATTN_SMEM (2 * NSTG * 64 * AKP * 2)  // 55296 B

__global__ __launch_bounds__(128, 2) void attn_h(
    const __half* __restrict__ Q, const __half* __restrict__ K,
    const __half* __restrict__ V, __half* __restrict__ O)
{
    extern __shared__ __align__(16) __half smh[];
    __half* Ks = smh;
    __half* Vs = smh + NSTG * 64 * AKP;
    __half* Qst = smh;                       // overlay

    const int tid = threadIdx.x;
    const int lane = tid & 31;
    const int g = lane >> 2, tig = lane & 3;
    const int wid = tid >> 5;
    const int qb = wid * 32;                 // warp covers 32 q-rows

    const int b = blockIdx.y >> 4;
    const int h = blockIdx.y & 15;
    const int q0 = blockIdx.x * 128;
    const size_t base = (size_t)b * SEQ * D_MODEL + (size_t)h * DK;

    // Stage Q (already pre-scaled by the Q projection) — pure copy.
    for (int i = tid; i < 128 * 8; i += 128) {
        int r = i >> 3, c8 = (i & 7) * 8;
        *(uint4*)&Qst[r * AKP + c8] =
            *(const uint4*)(Q + base + (size_t)(q0 + r) * D_MODEL + c8);
    }
    __syncthreads();

    const uint32_t sQ = (uint32_t)__cvta_generic_to_shared(Qst);
    const uint32_t sK = (uint32_t)__cvta_generic_to_shared(Ks);
    const uint32_t sV = (uint32_t)__cvta_generic_to_shared(Vs);
    const int a_row = lane & 15;
    const int a_byt = (lane >> 4) << 4;
    const int b_row = (lane & 7) + ((lane >> 4) << 3);
    const int b_byt = ((lane >> 3) & 1) << 4;
    const int v_row = (lane & 7) + (((lane >> 3) & 1) << 3);
    const int v_byt = (lane >> 4) << 4;

    uint32_t qa[2][4][4];
#pragma unroll
    for (int mt = 0; mt < 2; mt++)
#pragma unroll
        for (int kk = 0; kk < 4; kk++)
            ldsm4(qa[mt][kk], sQ + (qb + mt * 16 + a_row) * (AKP * 2) + kk * 32 + a_byt);
    __syncthreads();

    auto load_blk = [&](int kb, int p) {
#pragma unroll
        for (int j = 0; j < 4; j++) {
            int slot = tid + j * 128;
            int r = slot >> 3, c8 = (slot & 7) * 8;
            const __half* kg = K + base + (size_t)(kb * 64 + r) * D_MODEL + c8;
            const __half* vg = V + base + (size_t)(kb * 64 + r) * D_MODEL + c8;
            cp_async16(&Ks[p * 64 * AKP + r * AKP + c8], kg);
            cp_async16(&Vs[p * 64 * AKP + r * AKP + c8], vg);
        }
        cp_commit();
    };
    load_blk(0, 0);
    load_blk(1, 1);

    float m[2][2], l[2][2];
    float oacc[2][8][4];
#pragma unroll
    for (int mt = 0; mt < 2; mt++) {
        m[mt][0] = -INFINITY; m[mt][1] = -INFINITY;
        l[mt][0] = 0.0f; l[mt][1] = 0.0f;
#pragma unroll
        for (int nt = 0; nt < 8; nt++)
#pragma unroll
            for (int i = 0; i < 4; i++) oacc[mt][nt][i] = 0.0f;
    }

    const int NB = SEQ / 64;  // 32
    for (int kb = 0; kb < NB; kb++) {
        const int p = kb % NSTG;
        if (kb < NB - 1) cp_wait<1>(); else cp_wait<0>();
        __syncthreads();
        if (kb + 2 < NB) load_blk(kb + 2, (kb + 2) % NSTG);

        // S = Q @ K^T (base-2 domain), fp32 accumulate
        float s[2][8][4];
#pragma unroll
        for (int mt = 0; mt < 2; mt++)
#pragma unroll
            for (int nt = 0; nt < 8; nt++)
#pragma unroll
                for (int i = 0; i < 4; i++) s[mt][nt][i] = 0.0f;

        const uint32_t kBase = sK + p * (64 * AKP * 2);
#pragma unroll
        for (int kk = 0; kk < 4; kk++) {
#pragma unroll
            for (int nt2 = 0; nt2 < 4; nt2++) {
                uint32_t ub[4];
                ldsm4(ub, kBase + (nt2 * 16 + b_row) * (AKP * 2) + kk * 32 + b_byt);
#pragma unroll
                for (int mt = 0; mt < 2; mt++) {
                    mma16(s[mt][nt2 * 2],     qa[mt][kk][0], qa[mt][kk][1], qa[mt][kk][2], qa[mt][kk][3], ub[0], ub[1]);
                    mma16(s[mt][nt2 * 2 + 1], qa[mt][kk][0], qa[mt][kk][1], qa[mt][kk][2], qa[mt][kk][3], ub[2], ub[3]);
                }
            }
        }

        // Online softmax per m-fragment
        uint32_t ph0[2][8], ph1[2][8];
#pragma unroll
        for (int mt = 0; mt < 2; mt++) {
            float rmax0 = -INFINITY, rmax1 = -INFINITY;
#pragma unroll
            for (int nt = 0; nt < 8; nt++) {
                rmax0 = fmaxf(rmax0, fmaxf(s[mt][nt][0], s[mt][nt][1]));
                rmax1 = fmaxf(rmax1, fmaxf(s[mt][nt][2], s[mt][nt][3]));
            }
            rmax0 = fmaxf(rmax0, __shfl_xor_sync(0xffffffffu, rmax0, 1));
            rmax0 = fmaxf(rmax0, __shfl_xor_sync(0xffffffffu, rmax0, 2));
            rmax1 = fmaxf(rmax1, __shfl_xor_sync(0xffffffffu, rmax1, 1));
            rmax1 = fmaxf(rmax1, __shfl_xor_sync(0xffffffffu, rmax1, 2));

            const float mn0 = fmaxf(m[mt][0], rmax0);
            const float mn1 = fmaxf(m[mt][1], rmax1);
            const float alpha0 = exp2f(m[mt][0] - mn0);
            const float alpha1 = exp2f(m[mt][1] - mn1);

            float rs0 = 0.0f, rs1 = 0.0f;
#pragma unroll
            for (int nt = 0; nt < 8; nt++) {
                ph0[mt][nt] = ex2h2(packh2(s[mt][nt][0] - mn0, s[mt][nt][1] - mn0));
                ph1[mt][nt] = ex2h2(packh2(s[mt][nt][2] - mn1, s[mt][nt][3] - mn1));
                float2 f0 = __half22float2(*(__half2*)&ph0[mt][nt]);
                float2 f1 = __half22float2(*(__half2*)&ph1[mt][nt]);
                rs0 += f0.x + f0.y;
                rs1 += f1.x + f1.y;
            }
            rs0 += __shfl_xor_sync(0xffffffffu, rs0, 1);
            rs0 += __shfl_xor_sync(0xffffffffu, rs0, 2);
            rs1 += __shfl_xor_sync(0xffffffffu, rs1, 1);
            rs1 += __shfl_xor_sync(0xffffffffu, rs1, 2);

            l[mt][0] = l[mt][0] * alpha0 + rs0;
            l[mt][1] = l[mt][1] * alpha1 + rs1;
            m[mt][0] = mn0; m[mt][1] = mn1;
#pragma unroll
            for (int nt = 0; nt < 8; nt++) {
                oacc[mt][nt][0] *= alpha0; oacc[mt][nt][1] *= alpha0;
                oacc[mt][nt][2] *= alpha1; oacc[mt][nt][3] *= alpha1;
            }
        }

        // PV: A-frags = ph (fp16 already); V B-frags ldsm.trans shared over mt.
        const uint32_t vBase = sV + p * (64 * AKP * 2);
#pragma unroll
        for (int kk = 0; kk < 4; kk++) {
#pragma unroll
            for (int nt2 = 0; nt2 < 4; nt2++) {
                uint32_t ub[4];
                ldsm4t(ub, vBase + (kk * 16 + v_row) * (AKP * 2) + nt2 * 32 + v_byt);
#pragma unroll
                for (int mt = 0; mt < 2; mt++) {
                    mma16(oacc[mt][nt2 * 2],     ph0[mt][2 * kk], ph1[mt][2 * kk],
                          ph0[mt][2 * kk + 1], ph1[mt][2 * kk + 1], ub[0], ub[1]);
                    mma16(oacc[mt][nt2 * 2 + 1], ph0[mt][2 * kk], ph1[mt][2 * kk],
                          ph0[mt][2 * kk + 1], ph1[mt][2 * kk + 1], ub[2], ub[3]);
                }
            }
        }
    }

#pragma unroll
    for (int mt = 0; mt < 2; mt++) {
        const float inv0 = 1.0f / l[mt][0];
        const float inv1 = 1.0f / l[mt][1];
#pragma unroll
        for (int nt = 0; nt < 8; nt++) {
            const int col = nt * 8 + 2 * tig;
            __half* o0 = O + base + (size_t)(q0 + qb + mt * 16 + g) * D_MODEL + col;
            __half* o1 = O + base + (size_t)(q0 + qb + mt * 16 + g + 8) * D_MODEL + col;
            *(__half2*)o0 = __floats2half2_rn(oacc[mt][nt][0] * inv0, oacc[mt][nt][1] * inv0);
            *(__half2*)o1 = __floats2half2_rn(oacc[mt][nt][2] * inv1, oacc[mt][nt][3] * inv1);
        }
    }
}

// ---------------------------------------------------------------------------
// Launch
// ---------------------------------------------------------------------------
extern "C" void kernel_launch(void* const* d_in, const int* in_sizes, int n_in,
                              void* d_out, int out_size)
{
    const float* q  = (const float*)d_in[0];
    const float* k  = (const float*)d_in[1];
    const float* v  = (const float*)d_in[2];
    const float* Wq = (const float*)d_in[3];
    const float* bq = (const float*)d_in[4];
    const float* Wk = (const float*)d_in[5];
    const float* bk = (const float*)d_in[6];
    const float* Wv = (const float*)d_in[7];
    const float* bv = (const float*)d_in[8];
    const float* Wo = (const float*)d_in[9];
    const float* bo = (const float*)d_in[10];
    float* out = (float*)d_out;

    __half *pqh, *pkh, *pvh, *pQh, *pKh, *pVh, *pOh, *pWh;
    cudaGetSymbolAddress((void**)&pqh, g_qh);
    cudaGetSymbolAddress((void**)&pkh, g_kh);
    cudaGetSymbolAddress((void**)&pvh, g_vh);
    cudaGetSymbolAddress((void**)&pQh, g_Qh);
    cudaGetSymbolAddress((void**)&pKh, g_Kh);
    cudaGetSymbolAddress((void**)&pVh, g_Vh);
    cudaGetSymbolAddress((void**)&pOh, g_Oh);
    cudaGetSymbolAddress((void**)&pWh, g_Wh);

    cudaFuncSetAttribute(gemm_qkv, cudaFuncAttributeMaxDynamicSharedMemorySize,
                         GEMM_SMEM);
    cudaFuncSetAttribute(gemm_o, cudaFuncAttributeMaxDynamicSharedMemorySize,
                         GEMM_SMEM);
    cudaFuncSetAttribute(attn_h, cudaFuncAttributeMaxDynamicSharedMemorySize,
                         ATTN_SMEM);

    const int WN = D_MODEL * D_MODEL;
    const int XN = MTOT * D_MODEL;
    dim3 gX(XN / 2048, 3);
    cvt3_f2h<<<gX, 256>>>(q, k, v, pqh, pkh, pvh);
    dim3 gW(WN / 2048, 4);
    cvt4_f2h<<<gW, 256>>>(Wq, Wk, Wv, Wo, pWh);

    dim3 gQKV(D_MODEL / 128, MTOT / 128, 3);  // (8, 64, 3)
    gemm_qkv<<<gQKV, 128, GEMM_SMEM>>>(pqh, pkh, pvh, pWh,
                                       bq, bk, bv, pQh, pKh, pVh);

    dim3 gAttn(SEQ / 128, BATCH * NUM_HEADS);  // (16, 64)
    attn_h<<<gAttn, 128, ATTN_SMEM>>>(pQh, pKh, pVh, pOh);

    dim3 gGemm(D_MODEL / 128, MTOT / 128);  // (8, 64)
    gemm_o<<<gGemm, 128, GEMM_SMEM>>>(pOh, pWh + 3 * (size_t)WN, bo, out);
}